// round 15
// baseline (speedup 1.0000x reference)
#include <cuda_runtime.h>
#include <stdint.h>

// PNLoss: S=8192, N=2048, D=128, C=256 (32 members/class).
// logit[n,c] = -0.5*( q2 - 2*(s - del*q2)/den + (m2 - del*(2s-q2))/den^2 ),
//   den = max(cnt-del,0.1), masked 0 when cnt-del <= 0.1.
// loss = mean_n( lse_c(logit) - logit[n, y_n] ).

#define S_MAX 8192
#define N_MAX 2048
#define DIM   128
#define NC    256
#define CAP   40        // compacted member-list capacity
#define SEGC  20        // per-warp segment capacity (mean 4, P(overflow) ~ 1e-10)
#define QB    8         // queries per k2 block (measured best: grid 256)
#define K2B   (N_MAX / QB)   // 256

__device__ float g_cntf[NC];
__device__ __align__(16) float g_mus2[DIM * NC];  // [d][c] (class pairs contiguous)
__device__ float g_m2[NC];
__device__ int   g_ycls[N_MAX];
__device__ float g_part[K2B];
__device__ int   g_ticket;    // zeroed at load; k2's last block resets

// ---------------------------------------------------------------------------
// k_protos: block = class, 256 threads. 8 warps scan 1/8 of ys each
// (deterministic member order, no atomics/sort). Gather splits the member
// list across two thread-halves (one MLP-16 DRAM batch each), combined in
// fixed order. Each block fills g_ycls for its 8 queries.
// Early PDL trigger: lets k2 launch + stage xq while we gather.
// ---------------------------------------------------------------------------
__global__ void __launch_bounds__(256)
k_protos(const float* __restrict__ xs,
         const void*  __restrict__ ys_raw,
         const void*  __restrict__ pos_raw,
         int S, int N)
{
    __shared__ int   s_flags;           // bit0: ys int64, bit1: pos int64
    __shared__ int   seg[8][SEGC];
    __shared__ int   segcnt[8];
    __shared__ int   segoff[8];
    __shared__ int   s_list[CAP];
    __shared__ int   s_cnt;
    __shared__ float s_half[2][DIM];
    __shared__ float wsum[4];

    const int tid  = threadIdx.x;
    const int bid  = blockIdx.x;
    const int warp = tid >> 5, lane = tid & 31;
    const int c    = bid;

    // early trigger: all blocks are resident in wave 1, so the dependent k2
    // grid may launch now and overlap its xq staging with our gather below.
    cudaTriggerProgrammaticLaunchCompletion();

    // dtype detection: int32 read as int64 packs two values -> OOR w.h.p.
    if (tid == 0) s_flags = 3;
    __syncthreads();
    if (tid < 64) {
        if (tid < S) {
            long long v = ((const long long*)ys_raw)[tid];
            if (v < 0 || v >= NC) atomicAnd(&s_flags, ~1);
        }
        if (tid < N) {
            long long p = ((const long long*)pos_raw)[tid];
            if (p < 0 || p >= S) atomicAnd(&s_flags, ~2);
        }
    }
    __syncthreads();
    const int ys64 = s_flags & 1, pos64 = s_flags & 2;

    // side duty: this block's QB queries -> g_ycls[n] = ys[pos[n]]
    if (tid >= 128 && tid < 128 + QB) {
        int n = bid * QB + (tid - 128);
        if (n < N) {
            long long p = pos64 ? ((const long long*)pos_raw)[n]
                                : (long long)((const int*)pos_raw)[n];
            int y = 0;
            if (p >= 0 && p < S)
                y = ys64 ? (int)((const long long*)ys_raw)[p]
                         : ((const int*)ys_raw)[p];
            g_ycls[n] = y;
        }
    }

    // membership scan: warp w scans contiguous 1/8 of ys (1024 elems)
    {
        const int chunk = (S + 7) >> 3;
        const int base  = warp * chunk;
        const int end   = min(base + chunk, S);
        int cnt_w = 0;
        int it = base;
        for (; it + 8 * 32 <= end; it += 8 * 32) {
            int v[8];
            #pragma unroll
            for (int u = 0; u < 8; u++) {
                int i = it + u * 32 + lane;
                v[u] = ys64 ? (int)((const long long*)ys_raw)[i]
                            : ((const int*)ys_raw)[i];
            }
            #pragma unroll
            for (int u = 0; u < 8; u++) {
                int i = it + u * 32 + lane;
                bool m = (v[u] == c);
                unsigned mask = __ballot_sync(0xffffffffu, m);
                if (m) {
                    int slot = cnt_w + __popc(mask & ((1u << lane) - 1u));
                    if (slot < SEGC) seg[warp][slot] = i;
                }
                cnt_w += __popc(mask);
            }
        }
        for (; it < end; it += 32) {
            int i = it + lane;
            int v = -1;
            if (i < end)
                v = ys64 ? (int)((const long long*)ys_raw)[i]
                         : ((const int*)ys_raw)[i];
            bool m = (v == c);
            unsigned mask = __ballot_sync(0xffffffffu, m);
            if (m) {
                int slot = cnt_w + __popc(mask & ((1u << lane) - 1u));
                if (slot < SEGC) seg[warp][slot] = i;
            }
            cnt_w += __popc(mask);
        }
        if (lane == 0) segcnt[warp] = min(cnt_w, SEGC);
    }
    __syncthreads();

    // compact segments into s_list (deterministic: warp order, then position)
    if (tid == 0) {
        int off = 0;
        #pragma unroll
        for (int w = 0; w < 8; w++) { segoff[w] = off; off += segcnt[w]; }
        s_cnt = min(off, CAP);
    }
    __syncthreads();
    if (tid < 8 * SEGC) {
        int w = tid / SEGC, i = tid % SEGC;
        if (i < segcnt[w]) {
            int dst = segoff[w] + i;
            if (dst < CAP) s_list[dst] = seg[w][i];
        }
    }
    __syncthreads();

    // gather: half h sums members [jbeg, jend); one MLP-16 batch per half
    {
        const int cnt  = s_cnt;
        const int mid  = cnt >> 1;
        const int half = tid >> 7;            // 0 or 1
        const int d    = tid & 127;           // dim
        const int jbeg = half ? mid : 0;
        const int jend = half ? cnt : mid;

        float acc = 0.0f;
        int j = jbeg;
        for (; j + 16 <= jend; j += 16) {
            float v[16];
            #pragma unroll
            for (int u = 0; u < 16; u++)
                v[u] = xs[(size_t)s_list[j + u] * DIM + d];
            #pragma unroll
            for (int u = 0; u < 16; u++) acc += v[u];
        }
        if (j < jend) {
            float v[16];
            int m = jend - j;
            #pragma unroll
            for (int u = 0; u < 16; u++)
                v[u] = (u < m) ? xs[(size_t)s_list[j + u] * DIM + d] : 0.0f;
            #pragma unroll
            for (int u = 0; u < 16; u++) acc += v[u];
        }
        s_half[half][d] = acc;
    }
    __syncthreads();

    if (tid < DIM) {
        float acc = s_half[0][tid] + s_half[1][tid];   // fixed combine order
        g_mus2[tid * NC + c] = acc;

        float a2 = acc * acc;
        #pragma unroll
        for (int o = 16; o > 0; o >>= 1) a2 += __shfl_xor_sync(0xffffffffu, a2, o);
        if (lane == 0) wsum[warp] = a2;
    }
    __syncthreads();
    if (tid == 0) {
        g_m2[c]   = wsum[0] + wsum[1] + wsum[2] + wsum[3];
        g_cntf[c] = (float)s_cnt;
    }
}

// ---------------------------------------------------------------------------
// k2_loss: 256 threads = 2 query-groups x 128 class-pair threads; group g
// handles queries g*4..g*4+3 over full D. Per d: 1 LDG.64 + 2 LDS.128 +
// 4 ffma2 = 7 instr / 8 MACs. PDL: xq staging prelude runs before
// cudaGridDependencySynchronize (overlaps k_protos).
// ---------------------------------------------------------------------------
__device__ __forceinline__ unsigned long long
ffma2(unsigned long long a, unsigned long long b, unsigned long long c)
{
    unsigned long long d;
    asm("fma.rn.f32x2 %0, %1, %2, %3;" : "=l"(d) : "l"(a), "l"(b), "l"(c));
    return d;
}

__device__ __forceinline__ float
logit_fn(float s, float q2, float cnt, float m2, bool isy)
{
    float del = isy ? 1.0f : 0.0f;
    float dd  = cnt - del;
    float den = fmaxf(dd, 0.1f);
    float inv = 1.0f / den;
    float sp  = s - del * q2;
    float m2p = m2 - del * (2.0f * s - q2);
    float dist = q2 - 2.0f * sp * inv + m2p * inv * inv;
    return (dd > 0.1f) ? (-0.5f * dist) : 0.0f;
}

__global__ void __launch_bounds__(256, 4)
k2_loss(const float* __restrict__ xq, float* out, int N, int nblk)
{
    __shared__ __align__(16) float2 xqdup[DIM][QB];   // 8 KB: (x,x) duplicated
    __shared__ float logits[QB][NC];                  // 8 KB
    __shared__ float q2s[QB];
    __shared__ int   ycls[QB];
    __shared__ float part[QB];
    __shared__ float red[64];
    __shared__ int   s_last;

    const int tid   = threadIdx.x;
    const int bid   = blockIdx.x;
    const int qbase = bid * QB;
    const int w = tid >> 5, lane = tid & 31;
    const int grp = tid >> 7;          // query group 0/1
    const int cp  = tid & 127;         // class pair index

    // ---- PDL prelude: depends only on xq ----
    // stage query tile duplicated: (x,x) per element, [d][q]
    {
        int q = tid >> 5, j = tid & 31;    // 256 threads = QB*32 exactly
        int n = qbase + q;
        float4 v = make_float4(0.f, 0.f, 0.f, 0.f);
        if (n < N) v = reinterpret_cast<const float4*>(xq)[(size_t)n * 32 + j];
        xqdup[4*j+0][q] = make_float2(v.x, v.x);
        xqdup[4*j+1][q] = make_float2(v.y, v.y);
        xqdup[4*j+2][q] = make_float2(v.z, v.z);
        xqdup[4*j+3][q] = make_float2(v.w, v.w);
        float s = v.x*v.x + v.y*v.y + v.z*v.z + v.w*v.w;
        #pragma unroll
        for (int o = 16; o > 0; o >>= 1) s += __shfl_xor_sync(0xffffffffu, s, o);
        if (j == 0) q2s[q] = s;
    }

    // wait for k_protos results (g_mus2, g_m2, g_cntf, g_ycls)
    cudaGridDependencySynchronize();

    if (tid < QB) {
        int n = qbase + tid;
        ycls[tid] = (n < N) ? g_ycls[n] : 0;
    }
    // hoist epilogue constants: latency absorbed by the mainloop below
    const float2 cnt2 = reinterpret_cast<const float2*>(g_cntf)[cp];
    const float2 m22  = reinterpret_cast<const float2*>(g_m2)[cp];
    __syncthreads();

    // mainloop: group g, class pair cp; acc over full D for 4 queries
    const unsigned long long* mup =
        reinterpret_cast<const unsigned long long*>(g_mus2) + cp;
    const ulonglong2* xd =
        reinterpret_cast<const ulonglong2*>(xqdup) + 2 * grp;

    unsigned long long a0 = 0ull, a1 = 0ull, a2 = 0ull, a3 = 0ull;
    #pragma unroll 8
    for (int d = 0; d < DIM; d++) {
        unsigned long long mu = *mup;                // LDG.64, L2-resident
        mup += NC / 2;                               // pure pointer increment
        ulonglong2 x01 = xd[d * 4 + 0];              // queries g*4, g*4+1
        ulonglong2 x23 = xd[d * 4 + 1];              // queries g*4+2, g*4+3
        a0 = ffma2(mu, x01.x, a0);
        a1 = ffma2(mu, x01.y, a1);
        a2 = ffma2(mu, x23.x, a2);
        a3 = ffma2(mu, x23.y, a3);
    }

    // epilogue: logits for this group's 4 queries
    {
        const int c0 = 2 * cp, c1 = 2 * cp + 1;
        unsigned long long accs[4] = {a0, a1, a2, a3};
        #pragma unroll
        for (int qq = 0; qq < 4; qq++) {
            int q = grp * 4 + qq;
            float s0 = __uint_as_float((unsigned)(accs[qq] & 0xffffffffull));
            float s1 = __uint_as_float((unsigned)(accs[qq] >> 32));
            float qsq = q2s[q];
            int   yc  = ycls[q];
            float l0 = logit_fn(s0, qsq, cnt2.x, m22.x, c0 == yc);
            float l1 = logit_fn(s1, qsq, cnt2.y, m22.y, c1 == yc);
            reinterpret_cast<float2*>(&logits[q][0])[cp] = make_float2(l0, l1);
        }
    }
    __syncthreads();

    // LSE: warp w -> query w (8 classes/lane)
    {
        int n = qbase + w;
        float vv[8];
        float m = -1e30f;
        #pragma unroll
        for (int k = 0; k < 8; k++) {
            vv[k] = logits[w][lane + 32 * k];
            m = fmaxf(m, vv[k]);
        }
        #pragma unroll
        for (int o = 16; o > 0; o >>= 1) m = fmaxf(m, __shfl_xor_sync(0xffffffffu, m, o));
        float sum = 0.0f;
        #pragma unroll
        for (int k = 0; k < 8; k++) sum += __expf(vv[k] - m);
        #pragma unroll
        for (int o = 16; o > 0; o >>= 1) sum += __shfl_xor_sync(0xffffffffu, sum, o);
        if (lane == 0)
            part[w] = (n < N) ? (m + __logf(sum) - logits[w][ycls[w]]) : 0.0f;
    }
    __syncthreads();

    // deterministic cross-block reduction (ticket-elected last block)
    if (tid == 0) {
        float tot = 0.0f;
        #pragma unroll
        for (int q = 0; q < QB; q++) tot += part[q];
        g_part[bid] = tot;
        __threadfence();
        int tk = atomicAdd(&g_ticket, 1);
        s_last = (tk == nblk - 1) ? 1 : 0;
    }
    __syncthreads();
    if (s_last) {
        if (tid < 64) {
            float acc = 0.0f;
            for (int i = tid; i < nblk; i += 64) acc += g_part[i];
            red[tid] = acc;
        }
        __syncthreads();
        if (tid < 32) {
            float acc = red[tid] + red[tid + 32];
            #pragma unroll
            for (int o = 16; o > 0; o >>= 1)
                acc += __shfl_xor_sync(0xffffffffu, acc, o);
            if (tid == 0) {
                out[0]   = acc / (float)N;
                g_ticket = 0;   // replay invariant
            }
        }
    }
}

// ---------------------------------------------------------------------------
extern "C" void kernel_launch(void* const* d_in, const int* in_sizes, int n_in,
                              void* d_out, int out_size)
{
    const float* xq  = (const float*)d_in[0];
    const float* xs  = (const float*)d_in[2];
    const void*  ys  = d_in[3];
    const void*  pos = d_in[4];
    float* out = (float*)d_out;

    int N = in_sizes[1];
    int S = in_sizes[3];
    if (N > N_MAX) N = N_MAX;
    if (S > S_MAX) S = S_MAX;

    k_protos<<<NC, 256>>>(xs, ys, pos, S, N);

    int nblk = (N + QB - 1) / QB;
    cudaLaunchConfig_t cfg = {};
    cfg.gridDim  = dim3((unsigned)nblk, 1, 1);
    cfg.blockDim = dim3(256, 1, 1);
    cfg.dynamicSmemBytes = 0;
    cfg.stream = 0;                       // legacy default stream (captured)
    cudaLaunchAttribute attrs[1];
    attrs[0].id = cudaLaunchAttributeProgrammaticStreamSerialization;
    attrs[0].val.programmaticStreamSerializationAllowed = 1;
    cfg.attrs = attrs;
    cfg.numAttrs = 1;
    cudaLaunchKernelEx(&cfg, k2_loss, xq, out, N, nblk);
}

// round 16
// speedup vs baseline: 1.3792x; 1.3792x over previous
#include <cuda_runtime.h>
#include <stdint.h>

// PNLoss: S=8192, N=2048, D=128, C=256 (32 members/class).
// logit[n,c] = -0.5*( q2 - 2*(s - del*q2)/den + (m2 - del*(2s-q2))/den^2 ),
//   den = max(cnt-del,0.1), masked 0 when cnt-del <= 0.1.
// loss = mean_n( lse_c(logit) - logit[n, y_n] ).
//
// R14 configuration (measured best, 20.99us):
//  - k_protos: per-class ys scan (deterministic, no atomics), split gather.
//    NO early PDL trigger (R15 showed early trigger causes residency
//    contention: dependent blocks spin-wait and starve the producer).
//  - k2: QB=8/grid=256, launch_bounds(256,4), f32x2 FMA mainloop,
//    PDL with implicit completion trigger + prelude staging overlap.

#define S_MAX 8192
#define N_MAX 2048
#define DIM   128
#define NC    256
#define CAP   40        // compacted member-list capacity
#define SEGC  20        // per-warp segment capacity (mean 4, P(overflow) ~ 1e-10)
#define QB    8         // queries per k2 block (measured best: grid 256)
#define K2B   (N_MAX / QB)   // 256

__device__ float g_cntf[NC];
__device__ __align__(16) float g_mus2[DIM * NC];  // [d][c] (class pairs contiguous)
__device__ float g_m2[NC];
__device__ int   g_ycls[N_MAX];
__device__ float g_part[K2B];
__device__ int   g_ticket;    // zeroed at load; k2's last block resets

// ---------------------------------------------------------------------------
// k_protos: block = class, 256 threads. 8 warps scan 1/8 of ys each
// (deterministic member order, no atomics/sort). Gather splits the member
// list across two thread-halves (one MLP-16 DRAM batch each), combined in
// fixed order. Each block fills g_ycls for its 8 queries.
// ---------------------------------------------------------------------------
__global__ void __launch_bounds__(256)
k_protos(const float* __restrict__ xs,
         const void*  __restrict__ ys_raw,
         const void*  __restrict__ pos_raw,
         int S, int N)
{
    __shared__ int   s_flags;           // bit0: ys int64, bit1: pos int64
    __shared__ int   seg[8][SEGC];
    __shared__ int   segcnt[8];
    __shared__ int   segoff[8];
    __shared__ int   s_list[CAP];
    __shared__ int   s_cnt;
    __shared__ float s_half[2][DIM];
    __shared__ float wsum[4];

    const int tid  = threadIdx.x;
    const int bid  = blockIdx.x;
    const int warp = tid >> 5, lane = tid & 31;
    const int c    = bid;

    // dtype detection: int32 read as int64 packs two values -> OOR w.h.p.
    if (tid == 0) s_flags = 3;
    __syncthreads();
    if (tid < 64) {
        if (tid < S) {
            long long v = ((const long long*)ys_raw)[tid];
            if (v < 0 || v >= NC) atomicAnd(&s_flags, ~1);
        }
        if (tid < N) {
            long long p = ((const long long*)pos_raw)[tid];
            if (p < 0 || p >= S) atomicAnd(&s_flags, ~2);
        }
    }
    __syncthreads();
    const int ys64 = s_flags & 1, pos64 = s_flags & 2;

    // side duty: this block's QB queries -> g_ycls[n] = ys[pos[n]]
    if (tid >= 128 && tid < 128 + QB) {
        int n = bid * QB + (tid - 128);
        if (n < N) {
            long long p = pos64 ? ((const long long*)pos_raw)[n]
                                : (long long)((const int*)pos_raw)[n];
            int y = 0;
            if (p >= 0 && p < S)
                y = ys64 ? (int)((const long long*)ys_raw)[p]
                         : ((const int*)ys_raw)[p];
            g_ycls[n] = y;
        }
    }

    // membership scan: warp w scans contiguous 1/8 of ys (1024 elems)
    {
        const int chunk = (S + 7) >> 3;
        const int base  = warp * chunk;
        const int end   = min(base + chunk, S);
        int cnt_w = 0;
        int it = base;
        for (; it + 8 * 32 <= end; it += 8 * 32) {
            int v[8];
            #pragma unroll
            for (int u = 0; u < 8; u++) {
                int i = it + u * 32 + lane;
                v[u] = ys64 ? (int)((const long long*)ys_raw)[i]
                            : ((const int*)ys_raw)[i];
            }
            #pragma unroll
            for (int u = 0; u < 8; u++) {
                int i = it + u * 32 + lane;
                bool m = (v[u] == c);
                unsigned mask = __ballot_sync(0xffffffffu, m);
                if (m) {
                    int slot = cnt_w + __popc(mask & ((1u << lane) - 1u));
                    if (slot < SEGC) seg[warp][slot] = i;
                }
                cnt_w += __popc(mask);
            }
        }
        for (; it < end; it += 32) {
            int i = it + lane;
            int v = -1;
            if (i < end)
                v = ys64 ? (int)((const long long*)ys_raw)[i]
                         : ((const int*)ys_raw)[i];
            bool m = (v == c);
            unsigned mask = __ballot_sync(0xffffffffu, m);
            if (m) {
                int slot = cnt_w + __popc(mask & ((1u << lane) - 1u));
                if (slot < SEGC) seg[warp][slot] = i;
            }
            cnt_w += __popc(mask);
        }
        if (lane == 0) segcnt[warp] = min(cnt_w, SEGC);
    }
    __syncthreads();

    // compact segments into s_list (deterministic: warp order, then position)
    if (tid == 0) {
        int off = 0;
        #pragma unroll
        for (int w = 0; w < 8; w++) { segoff[w] = off; off += segcnt[w]; }
        s_cnt = min(off, CAP);
    }
    __syncthreads();
    if (tid < 8 * SEGC) {
        int w = tid / SEGC, i = tid % SEGC;
        if (i < segcnt[w]) {
            int dst = segoff[w] + i;
            if (dst < CAP) s_list[dst] = seg[w][i];
        }
    }
    __syncthreads();

    // gather: half h sums members [jbeg, jend); one MLP-16 batch per half
    {
        const int cnt  = s_cnt;
        const int mid  = cnt >> 1;
        const int half = tid >> 7;            // 0 or 1
        const int d    = tid & 127;           // dim
        const int jbeg = half ? mid : 0;
        const int jend = half ? cnt : mid;

        float acc = 0.0f;
        int j = jbeg;
        for (; j + 16 <= jend; j += 16) {
            float v[16];
            #pragma unroll
            for (int u = 0; u < 16; u++)
                v[u] = xs[(size_t)s_list[j + u] * DIM + d];
            #pragma unroll
            for (int u = 0; u < 16; u++) acc += v[u];
        }
        if (j < jend) {
            float v[16];
            int m = jend - j;
            #pragma unroll
            for (int u = 0; u < 16; u++)
                v[u] = (u < m) ? xs[(size_t)s_list[j + u] * DIM + d] : 0.0f;
            #pragma unroll
            for (int u = 0; u < 16; u++) acc += v[u];
        }
        s_half[half][d] = acc;
    }
    __syncthreads();

    if (tid < DIM) {
        float acc = s_half[0][tid] + s_half[1][tid];   // fixed combine order
        g_mus2[tid * NC + c] = acc;

        float a2 = acc * acc;
        #pragma unroll
        for (int o = 16; o > 0; o >>= 1) a2 += __shfl_xor_sync(0xffffffffu, a2, o);
        if (lane == 0) wsum[warp] = a2;
    }
    __syncthreads();
    if (tid == 0) {
        g_m2[c]   = wsum[0] + wsum[1] + wsum[2] + wsum[3];
        g_cntf[c] = (float)s_cnt;
    }
}

// ---------------------------------------------------------------------------
// k2_loss: 256 threads = 2 query-groups x 128 class-pair threads; group g
// handles queries g*4..g*4+3 over full D. Per d: 1 LDG.64 + 2 LDS.128 +
// 4 ffma2 = 7 instr / 8 MACs. PDL: xq staging prelude runs before
// cudaGridDependencySynchronize (overlaps k_protos' tail/launch latency).
// ---------------------------------------------------------------------------
__device__ __forceinline__ unsigned long long
ffma2(unsigned long long a, unsigned long long b, unsigned long long c)
{
    unsigned long long d;
    asm("fma.rn.f32x2 %0, %1, %2, %3;" : "=l"(d) : "l"(a), "l"(b), "l"(c));
    return d;
}

__device__ __forceinline__ float
logit_fn(float s, float q2, float cnt, float m2, bool isy)
{
    float del = isy ? 1.0f : 0.0f;
    float dd  = cnt - del;
    float den = fmaxf(dd, 0.1f);
    float inv = 1.0f / den;
    float sp  = s - del * q2;
    float m2p = m2 - del * (2.0f * s - q2);
    float dist = q2 - 2.0f * sp * inv + m2p * inv * inv;
    return (dd > 0.1f) ? (-0.5f * dist) : 0.0f;
}

__global__ void __launch_bounds__(256, 4)
k2_loss(const float* __restrict__ xq, float* out, int N, int nblk)
{
    __shared__ __align__(16) float2 xqdup[DIM][QB];   // 8 KB: (x,x) duplicated
    __shared__ float logits[QB][NC];                  // 8 KB
    __shared__ float q2s[QB];
    __shared__ int   ycls[QB];
    __shared__ float part[QB];
    __shared__ float red[64];
    __shared__ int   s_last;

    const int tid   = threadIdx.x;
    const int bid   = blockIdx.x;
    const int qbase = bid * QB;
    const int w = tid >> 5, lane = tid & 31;
    const int grp = tid >> 7;          // query group 0/1
    const int cp  = tid & 127;         // class pair index

    // ---- PDL prelude: depends only on xq ----
    // stage query tile duplicated: (x,x) per element, [d][q]
    {
        int q = tid >> 5, j = tid & 31;    // 256 threads = QB*32 exactly
        int n = qbase + q;
        float4 v = make_float4(0.f, 0.f, 0.f, 0.f);
        if (n < N) v = reinterpret_cast<const float4*>(xq)[(size_t)n * 32 + j];
        xqdup[4*j+0][q] = make_float2(v.x, v.x);
        xqdup[4*j+1][q] = make_float2(v.y, v.y);
        xqdup[4*j+2][q] = make_float2(v.z, v.z);
        xqdup[4*j+3][q] = make_float2(v.w, v.w);
        float s = v.x*v.x + v.y*v.y + v.z*v.z + v.w*v.w;
        #pragma unroll
        for (int o = 16; o > 0; o >>= 1) s += __shfl_xor_sync(0xffffffffu, s, o);
        if (j == 0) q2s[q] = s;
    }

    // wait for k_protos results (g_mus2, g_m2, g_cntf, g_ycls)
    cudaGridDependencySynchronize();

    if (tid < QB) {
        int n = qbase + tid;
        ycls[tid] = (n < N) ? g_ycls[n] : 0;
    }
    // hoist epilogue constants: latency absorbed by the mainloop below
    const float2 cnt2 = reinterpret_cast<const float2*>(g_cntf)[cp];
    const float2 m22  = reinterpret_cast<const float2*>(g_m2)[cp];
    __syncthreads();

    // mainloop: group g, class pair cp; acc over full D for 4 queries
    const unsigned long long* mup =
        reinterpret_cast<const unsigned long long*>(g_mus2) + cp;
    const ulonglong2* xd =
        reinterpret_cast<const ulonglong2*>(xqdup) + 2 * grp;

    unsigned long long a0 = 0ull, a1 = 0ull, a2 = 0ull, a3 = 0ull;
    #pragma unroll 8
    for (int d = 0; d < DIM; d++) {
        unsigned long long mu = *mup;                // LDG.64, L2-resident
        mup += NC / 2;                               // pure pointer increment
        ulonglong2 x01 = xd[d * 4 + 0];              // queries g*4, g*4+1
        ulonglong2 x23 = xd[d * 4 + 1];              // queries g*4+2, g*4+3
        a0 = ffma2(mu, x01.x, a0);
        a1 = ffma2(mu, x01.y, a1);
        a2 = ffma2(mu, x23.x, a2);
        a3 = ffma2(mu, x23.y, a3);
    }

    // epilogue: logits for this group's 4 queries
    {
        const int c0 = 2 * cp, c1 = 2 * cp + 1;
        unsigned long long accs[4] = {a0, a1, a2, a3};
        #pragma unroll
        for (int qq = 0; qq < 4; qq++) {
            int q = grp * 4 + qq;
            float s0 = __uint_as_float((unsigned)(accs[qq] & 0xffffffffull));
            float s1 = __uint_as_float((unsigned)(accs[qq] >> 32));
            float qsq = q2s[q];
            int   yc  = ycls[q];
            float l0 = logit_fn(s0, qsq, cnt2.x, m22.x, c0 == yc);
            float l1 = logit_fn(s1, qsq, cnt2.y, m22.y, c1 == yc);
            reinterpret_cast<float2*>(&logits[q][0])[cp] = make_float2(l0, l1);
        }
    }
    __syncthreads();

    // LSE: warp w -> query w (8 classes/lane)
    {
        int n = qbase + w;
        float vv[8];
        float m = -1e30f;
        #pragma unroll
        for (int k = 0; k < 8; k++) {
            vv[k] = logits[w][lane + 32 * k];
            m = fmaxf(m, vv[k]);
        }
        #pragma unroll
        for (int o = 16; o > 0; o >>= 1) m = fmaxf(m, __shfl_xor_sync(0xffffffffu, m, o));
        float sum = 0.0f;
        #pragma unroll
        for (int k = 0; k < 8; k++) sum += __expf(vv[k] - m);
        #pragma unroll
        for (int o = 16; o > 0; o >>= 1) sum += __shfl_xor_sync(0xffffffffu, sum, o);
        if (lane == 0)
            part[w] = (n < N) ? (m + __logf(sum) - logits[w][ycls[w]]) : 0.0f;
    }
    __syncthreads();

    // deterministic cross-block reduction (ticket-elected last block)
    if (tid == 0) {
        float tot = 0.0f;
        #pragma unroll
        for (int q = 0; q < QB; q++) tot += part[q];
        g_part[bid] = tot;
        __threadfence();
        int tk = atomicAdd(&g_ticket, 1);
        s_last = (tk == nblk - 1) ? 1 : 0;
    }
    __syncthreads();
    if (s_last) {
        if (tid < 64) {
            float acc = 0.0f;
            for (int i = tid; i < nblk; i += 64) acc += g_part[i];
            red[tid] = acc;
        }
        __syncthreads();
        if (tid < 32) {
            float acc = red[tid] + red[tid + 32];
            #pragma unroll
            for (int o = 16; o > 0; o >>= 1)
                acc += __shfl_xor_sync(0xffffffffu, acc, o);
            if (tid == 0) {
                out[0]   = acc / (float)N;
                g_ticket = 0;   // replay invariant
            }
        }
    }
}

// ---------------------------------------------------------------------------
extern "C" void kernel_launch(void* const* d_in, const int* in_sizes, int n_in,
                              void* d_out, int out_size)
{
    const float* xq  = (const float*)d_in[0];
    const float* xs  = (const float*)d_in[2];
    const void*  ys  = d_in[3];
    const void*  pos = d_in[4];
    float* out = (float*)d_out;

    int N = in_sizes[1];
    int S = in_sizes[3];
    if (N > N_MAX) N = N_MAX;
    if (S > S_MAX) S = S_MAX;

    k_protos<<<NC, 256>>>(xs, ys, pos, S, N);

    int nblk = (N + QB - 1) / QB;
    cudaLaunchConfig_t cfg = {};
    cfg.gridDim  = dim3((unsigned)nblk, 1, 1);
    cfg.blockDim = dim3(256, 1, 1);
    cfg.dynamicSmemBytes = 0;
    cfg.stream = 0;                       // legacy default stream (captured)
    cudaLaunchAttribute attrs[1];
    attrs[0].id = cudaLaunchAttributeProgrammaticStreamSerialization;
    attrs[0].val.programmaticStreamSerializationAllowed = 1;
    cfg.attrs = attrs;
    cfg.numAttrs = 1;
    cudaLaunchKernelEx(&cfg, k2_loss, xq, out, N, nblk);
}